// round 1
// baseline (speedup 1.0000x reference)
#include <cuda_runtime.h>

#define NN 100000
#define EE 3200000
#define GG 2048
#define FIN 9
#define HF 64
#define ZC 96            // H + EXTRA
#define EXTRA_F 32
#define BN_EPS 1e-5f
#define NB_SCAN ((NN + 1023) / 1024)   // 98

// ---------------- scratch (device globals; no allocation allowed) -------------
__device__ __align__(16) float g_u[NN * HF];     // dis-scaled transformed features
__device__ __align__(16) float g_h[NN * HF];     // layer activations
__device__ int   g_indeg[NN];
__device__ int   g_rowptr[NN + 1];
__device__ int   g_cursor[NN];
__device__ int   g_csr[EE];
__device__ float g_dis[NN];
__device__ int   g_bsum[128];
__device__ int   g_carry[128];
__device__ float g_z[GG * ZC];
__device__ float g_cnt[GG];
__device__ float g_y0[GG * 128];
__device__ float g_y1[GG * 64];
__device__ float g_y2[GG * 32];
__device__ float g_colsum[128];
__device__ float g_colsq[128];
__device__ float g_scale[128];
__device__ float g_shift[128];

// ---------------- init / CSR build -------------------------------------------
__global__ void k_init() {
    int t = blockIdx.x * blockDim.x + threadIdx.x;
    if (t < NN) g_indeg[t] = 0;
    if (t < GG * ZC) g_z[t] = 0.f;
    if (t < GG) g_cnt[t] = 0.f;
}

__global__ void k_hist(const int* __restrict__ dst) {
    int e = blockIdx.x * blockDim.x + threadIdx.x;
    if (e < EE) atomicAdd(&g_indeg[dst[e]], 1);
}

__global__ void k_dis() {
    int i = blockIdx.x * blockDim.x + threadIdx.x;
    if (i < NN) g_dis[i] = rsqrtf((float)(g_indeg[i] + 1));   // +1 self loop
}

__global__ void k_scan1() {
    __shared__ int s[1024];
    int gid = blockIdx.x * 1024 + threadIdx.x;
    int v = (gid < NN) ? g_indeg[gid] : 0;
    s[threadIdx.x] = v;
    __syncthreads();
    for (int off = 1; off < 1024; off <<= 1) {
        int t = (threadIdx.x >= off) ? s[threadIdx.x - off] : 0;
        __syncthreads();
        s[threadIdx.x] += t;
        __syncthreads();
    }
    if (gid < NN) g_rowptr[gid] = s[threadIdx.x] - v;   // exclusive (partial)
    if (threadIdx.x == 1023) g_bsum[blockIdx.x] = s[1023];
}

__global__ void k_scan2() {
    __shared__ int s[128];
    int t = threadIdx.x;
    int v = (t < NB_SCAN) ? g_bsum[t] : 0;
    s[t] = v;
    __syncthreads();
    for (int off = 1; off < 128; off <<= 1) {
        int u = (t >= off) ? s[t - off] : 0;
        __syncthreads();
        s[t] += u;
        __syncthreads();
    }
    g_carry[t] = s[t] - v;   // exclusive
}

__global__ void k_scan3() {
    int gid = blockIdx.x * blockDim.x + threadIdx.x;
    if (gid < NN) {
        int r = g_rowptr[gid] + g_carry[gid >> 10];
        g_rowptr[gid] = r;
        g_cursor[gid] = r;
    }
    if (gid == 0) g_rowptr[NN] = EE;
}

__global__ void k_scatter(const int* __restrict__ src, const int* __restrict__ dst) {
    int e = blockIdx.x * blockDim.x + threadIdx.x;
    if (e < EE) {
        int d = dst[e];
        int p = atomicAdd(&g_cursor[d], 1);
        g_csr[p] = src[e];
    }
}

// ---------------- GCN: transform (u = dis * (in @ W)) ------------------------
template <int K>
__global__ void k_transform(const float* __restrict__ in, const float* __restrict__ W,
                            float* __restrict__ out) {
    __shared__ float Ws[K * HF];
    __shared__ float hs[4 * K];
    for (int idx = threadIdx.x; idx < K * HF; idx += 256) Ws[idx] = W[idx];
    int c = threadIdx.x & 63;
    int r = threadIdx.x >> 6;        // 0..3 node lanes
    int base = blockIdx.x * 64;      // 64 nodes / block
    __syncthreads();
#pragma unroll 1
    for (int it = 0; it < 16; ++it) {
        int nb = base + it * 4;
        if (threadIdx.x < 4 * K) {
            int row = threadIdx.x / K, col = threadIdx.x - row * K;
            int node = nb + row;
            hs[threadIdx.x] = (node < NN) ? in[node * K + col] : 0.f;
        }
        __syncthreads();
        float acc = 0.f;
#pragma unroll
        for (int k = 0; k < K; ++k) acc = fmaf(hs[r * K + k], Ws[k * HF + c], acc);
        int node = nb + r;
        if (node < NN) out[node * HF + c] = g_dis[node] * acc;
        __syncthreads();
    }
}

// ---------------- GCN: aggregate (warp per node, gather CSR) -----------------
__global__ void k_aggregate(const float* __restrict__ bias) {
    int t = blockIdx.x * blockDim.x + threadIdx.x;
    int i = t >> 5;
    int lane = t & 31;
    if (i >= NN) return;
    const float2* __restrict__ u2 = (const float2*)g_u;
    float2 acc = u2[i * 32 + lane];          // self-loop term (u already dis-scaled)
    int j = g_rowptr[i], end = g_rowptr[i + 1];
    for (; j + 4 <= end; j += 4) {
        int s0 = g_csr[j], s1 = g_csr[j + 1], s2 = g_csr[j + 2], s3 = g_csr[j + 3];
        float2 a = u2[s0 * 32 + lane];
        float2 b = u2[s1 * 32 + lane];
        float2 c = u2[s2 * 32 + lane];
        float2 d = u2[s3 * 32 + lane];
        acc.x += (a.x + b.x) + (c.x + d.x);
        acc.y += (a.y + b.y) + (c.y + d.y);
    }
    for (; j < end; ++j) {
        int s = g_csr[j];
        float2 a = u2[s * 32 + lane];
        acc.x += a.x; acc.y += a.y;
    }
    float di = g_dis[i];
    float ox = fmaxf(fmaf(di, acc.x, bias[2 * lane]), 0.f);
    float oy = fmaxf(fmaf(di, acc.y, bias[2 * lane + 1]), 0.f);
    ((float2*)g_h)[i * 32 + lane] = make_float2(ox, oy);
}

// ---------------- global mean pool -------------------------------------------
__global__ void k_pool(const int* __restrict__ batch) {
    int t = blockIdx.x * blockDim.x + threadIdx.x;
    int i = t >> 5;
    int lane = t & 31;
    if (i >= NN) return;
    int g = batch[i];
    float2 v = ((const float2*)g_h)[i * 32 + lane];
    atomicAdd(&g_z[g * ZC + 2 * lane], v.x);
    atomicAdd(&g_z[g * ZC + 2 * lane + 1], v.y);
    if (lane == 0) atomicAdd(&g_cnt[g], 1.f);
}

__global__ void k_finz(const float* __restrict__ extra) {
    int t = blockIdx.x * blockDim.x + threadIdx.x;
    if (t >= GG * ZC) return;
    int g = t / ZC, c = t - g * ZC;
    if (c < HF) g_z[t] = g_z[t] / fmaxf(g_cnt[g], 1.f);
    else        g_z[t] = extra[g * EXTRA_F + (c - HF)];
}

// ---------------- MLP + BatchNorm --------------------------------------------
__global__ void k_zstat() {
    g_colsum[threadIdx.x] = 0.f;
    g_colsq[threadIdx.x] = 0.f;
}

template <int K, int C>
__global__ void k_mlp(const float* __restrict__ z, const float* __restrict__ W,
                      const float* __restrict__ b, float* __restrict__ y) {
    constexpr int RPT = 256 / C;
    __shared__ float Ws[K * C];
    for (int idx = threadIdx.x; idx < K * C; idx += 256) Ws[idx] = W[idx];
    __syncthreads();
    int c = threadIdx.x % C;
    int r0 = threadIdx.x / C;
    const int rowsPerBlock = GG / 16;
    int rbase = blockIdx.x * rowsPerBlock;
    float bc = b[c];
    float s1 = 0.f, s2 = 0.f;
    for (int rr = r0; rr < rowsPerBlock; rr += RPT) {
        int row = rbase + rr;
        const float* __restrict__ zr = z + row * K;
        float acc = bc;
#pragma unroll
        for (int k = 0; k < K; ++k) acc = fmaf(zr[k], Ws[k * C + c], acc);
        y[row * C + c] = acc;
        s1 += acc;
        s2 = fmaf(acc, acc, s2);
    }
    atomicAdd(&g_colsum[c], s1);
    atomicAdd(&g_colsq[c], s2);
}

template <int C>
__global__ void k_bnfin(const float* __restrict__ gam, const float* __restrict__ bet) {
    int c = threadIdx.x;
    if (c >= C) return;
    float mu = g_colsum[c] * (1.f / (float)GG);
    float var = g_colsq[c] * (1.f / (float)GG) - mu * mu;
    float sc = gam[c] * rsqrtf(var + BN_EPS);
    g_scale[c] = sc;
    g_shift[c] = bet[c] - mu * sc;
}

template <int C>
__global__ void k_bnapp(float* __restrict__ y) {
    int t = blockIdx.x * blockDim.x + threadIdx.x;
    if (t >= GG * C) return;
    int c = t % C;
    y[t] = fmaxf(fmaf(y[t], g_scale[c], g_shift[c]), 0.f);
}

__global__ void k_final(const float* __restrict__ W, const float* __restrict__ b,
                        float* __restrict__ out) {
    int t = blockIdx.x * blockDim.x + threadIdx.x;
    int g = t >> 5;
    int lane = t & 31;
    if (g >= GG) return;
    float v = g_y2[g * 32 + lane] * W[lane];
#pragma unroll
    for (int o = 16; o; o >>= 1) v += __shfl_xor_sync(0xFFFFFFFFu, v, o);
    if (lane == 0) out[g] = v + b[0];
}

// ---------------- launch -----------------------------------------------------
extern "C" void kernel_launch(void* const* d_in, const int* in_sizes, int n_in,
                              void* d_out, int out_size) {
    const float* x     = (const float*)d_in[0];
    const int*   ei    = (const int*)d_in[1];
    const int*   batch = (const int*)d_in[2];
    const float* extra = (const float*)d_in[3];
    const float* W1 = (const float*)d_in[4];  const float* b1 = (const float*)d_in[5];
    const float* W2 = (const float*)d_in[6];  const float* b2 = (const float*)d_in[7];
    const float* W3 = (const float*)d_in[8];  const float* b3 = (const float*)d_in[9];
    const float* Wm0 = (const float*)d_in[10]; const float* bm0 = (const float*)d_in[11];
    const float* g0  = (const float*)d_in[12]; const float* be0 = (const float*)d_in[13];
    const float* Wm1 = (const float*)d_in[14]; const float* bm1 = (const float*)d_in[15];
    const float* g1  = (const float*)d_in[16]; const float* be1 = (const float*)d_in[17];
    const float* Wm2 = (const float*)d_in[18]; const float* bm2 = (const float*)d_in[19];
    const float* g2  = (const float*)d_in[20]; const float* be2 = (const float*)d_in[21];
    const float* Wm3 = (const float*)d_in[22]; const float* bm3 = (const float*)d_in[23];
    float* out = (float*)d_out;

    const int* src = ei;
    const int* dst = ei + EE;

    float *p_u, *p_h, *p_y0, *p_y1, *p_y2;
    cudaGetSymbolAddress((void**)&p_u, g_u);
    cudaGetSymbolAddress((void**)&p_h, g_h);
    cudaGetSymbolAddress((void**)&p_y0, g_y0);
    cudaGetSymbolAddress((void**)&p_y1, g_y1);
    cudaGetSymbolAddress((void**)&p_y2, g_y2);
    float* p_z;
    cudaGetSymbolAddress((void**)&p_z, g_z);

    const int TB = 256;
    // init + CSR build
    k_init<<<(GG * ZC + TB - 1) / TB, TB>>>();
    k_hist<<<(EE + TB - 1) / TB, TB>>>(dst);
    k_dis<<<(NN + TB - 1) / TB, TB>>>();
    k_scan1<<<NB_SCAN, 1024>>>();
    k_scan2<<<1, 128>>>();
    k_scan3<<<(NN + TB - 1) / TB, TB>>>();
    k_scatter<<<(EE + TB - 1) / TB, TB>>>(src, dst);

    const int TGRID = (NN + 63) / 64;
    const int AGRID = (NN * 32 + TB - 1) / TB;

    // GCN layer 1
    k_transform<FIN><<<TGRID, TB>>>(x, W1, p_u);
    k_aggregate<<<AGRID, TB>>>(b1);
    // GCN layer 2
    k_transform<HF><<<TGRID, TB>>>(p_h, W2, p_u);
    k_aggregate<<<AGRID, TB>>>(b2);
    // GCN layer 3
    k_transform<HF><<<TGRID, TB>>>(p_h, W3, p_u);
    k_aggregate<<<AGRID, TB>>>(b3);

    // pool + concat extra
    k_pool<<<AGRID, TB>>>(batch);
    k_finz<<<(GG * ZC + TB - 1) / TB, TB>>>(extra);

    // MLP layer 0: [96 -> 128]
    k_zstat<<<1, 128>>>();
    k_mlp<96, 128><<<16, TB>>>(p_z, Wm0, bm0, p_y0);
    k_bnfin<128><<<1, 128>>>(g0, be0);
    k_bnapp<128><<<(GG * 128 + TB - 1) / TB, TB>>>(p_y0);

    // MLP layer 1: [128 -> 64]
    k_zstat<<<1, 128>>>();
    k_mlp<128, 64><<<16, TB>>>(p_y0, Wm1, bm1, p_y1);
    k_bnfin<64><<<1, 64>>>(g1, be1);
    k_bnapp<64><<<(GG * 64 + TB - 1) / TB, TB>>>(p_y1);

    // MLP layer 2: [64 -> 32]
    k_zstat<<<1, 128>>>();
    k_mlp<64, 32><<<16, TB>>>(p_y1, Wm2, bm2, p_y2);
    k_bnfin<32><<<1, 32>>>(g2, be2);
    k_bnapp<32><<<(GG * 32 + TB - 1) / TB, TB>>>(p_y2);

    // final linear [32 -> 1]
    k_final<<<(GG * 32 + TB - 1) / TB, TB>>>(Wm3, bm3, out);
}